// round 2
// baseline (speedup 1.0000x reference)
#include <cuda_runtime.h>
#include <mma.h>
#include <math.h>

using namespace nvcuda;

// Problem constants: B=4, N=4096, C=1024, h=16, d=64
// M = B*N = 16384 rows
#define BM 128
#define BN 128
#define BK 16

// Scratch (static __device__ globals; no allocations allowed)
__device__ float g_qkv[50331648];   // [16384, 3072]  (q|k|v), phi already applied to q,k
__device__ float g_attn[16777216];  // [16384, 1024]  attention output before proj
__device__ float g_kv_part[2097152];// [8 chunks][64 bh][64][64]
__device__ float g_ks_part[32768];  // [8][64][64]
__device__ float g_kv[262144];      // [64 bh][64][64]
__device__ float g_ks[4096];        // [64 bh][64]

// ---------------------------------------------------------------------------
// TF32 WMMA GEMM:  C[m,n] = sum_k A[m,k] * W[n,k]  (+bias[n])  (+phi on n<2048)
// A: [M,K] row-major, W: [N,K] row-major.
// Block tile 128x128, K-tile 16, 256 threads (8 warps: 4 in M x 2 in N),
// each warp computes 32x64 via 2x4 m16n16k8 fragments. Double-buffered smem.
// ---------------------------------------------------------------------------
template <bool DO_PHI, bool DO_BIAS>
__global__ __launch_bounds__(256) void gemm_tf32(
    const float* __restrict__ A, const float* __restrict__ W,
    const float* __restrict__ bias, float* __restrict__ C,
    int M, int N, int K)
{
    __shared__ __align__(16) float As[2][BM * BK];
    __shared__ __align__(16) float Bs[2][BN * BK];
    __shared__ float bias_sm[16 * BN];

    const int t  = threadIdx.x;
    const int n0 = blockIdx.x * BN;
    const int m0 = blockIdx.y * BM;
    const int warp = t >> 5;
    const int wm = warp & 3;   // warp row  (32 rows each)
    const int wn = warp >> 2;  // warp col  (64 cols each)

    const float* Ablk = A + (size_t)m0 * K;
    const float* Wblk = W + (size_t)n0 * K;

    wmma::fragment<wmma::accumulator, 16, 16, 8, float> c[2][4];

    if (DO_BIAS) {
        for (int i = t; i < 16 * BN; i += 256)
            bias_sm[i] = bias[n0 + (i & (BN - 1))];
        __syncthreads();
        #pragma unroll
        for (int i = 0; i < 2; i++)
            #pragma unroll
            for (int j = 0; j < 4; j++)
                wmma::load_matrix_sync(c[i][j], &bias_sm[wn * 64 + j * 16], BN,
                                       wmma::mem_row_major);
        __syncthreads();
    } else {
        #pragma unroll
        for (int i = 0; i < 2; i++)
            #pragma unroll
            for (int j = 0; j < 4; j++)
                wmma::fill_fragment(c[i][j], 0.0f);
    }

    // Each thread loads 2 float4 for A-tile and 2 for B-tile per K-step.
    int rr[2], cc[2];
    #pragma unroll
    for (int i = 0; i < 2; i++) {
        int slot = t + 256 * i;   // 512 float4 slots per 128x16 tile
        rr[i] = slot >> 2;
        cc[i] = (slot & 3) * 4;
    }
    float4 pa[2], pb[2];

    auto gload = [&](int kt) {
        int k0 = kt * BK;
        #pragma unroll
        for (int i = 0; i < 2; i++) {
            pa[i] = *(const float4*)(Ablk + (size_t)rr[i] * K + k0 + cc[i]);
            pb[i] = *(const float4*)(Wblk + (size_t)rr[i] * K + k0 + cc[i]);
        }
    };
    auto sstore = [&](int buf) {
        #pragma unroll
        for (int i = 0; i < 2; i++) {
            *(float4*)&As[buf][rr[i] * BK + cc[i]] = pa[i];
            *(float4*)&Bs[buf][rr[i] * BK + cc[i]] = pb[i];
        }
    };

    gload(0);
    sstore(0);
    __syncthreads();

    const int nk = K / BK;
    for (int kt = 0; kt < nk; ++kt) {
        const int cur = kt & 1;
        if (kt + 1 < nk) gload(kt + 1);

        #pragma unroll
        for (int kk = 0; kk < BK; kk += 8) {
            wmma::fragment<wmma::matrix_a, 16, 16, 8, wmma::precision::tf32,
                           wmma::row_major> a[2];
            wmma::fragment<wmma::matrix_b, 16, 16, 8, wmma::precision::tf32,
                           wmma::col_major> b[4];
            #pragma unroll
            for (int i = 0; i < 2; i++) {
                wmma::load_matrix_sync(a[i], &As[cur][(wm * 32 + i * 16) * BK + kk], BK);
                #pragma unroll
                for (int e = 0; e < a[i].num_elements; e++)
                    a[i].x[e] = wmma::__float_to_tf32(a[i].x[e]);
            }
            #pragma unroll
            for (int j = 0; j < 4; j++) {
                wmma::load_matrix_sync(b[j], &Bs[cur][(wn * 64 + j * 16) * BK + kk], BK);
                #pragma unroll
                for (int e = 0; e < b[j].num_elements; e++)
                    b[j].x[e] = wmma::__float_to_tf32(b[j].x[e]);
            }
            #pragma unroll
            for (int i = 0; i < 2; i++)
                #pragma unroll
                for (int j = 0; j < 4; j++)
                    wmma::mma_sync(c[i][j], a[i], b[j], c[i][j]);
        }

        if (kt + 1 < nk) sstore(cur ^ 1);
        __syncthreads();
    }

    const bool phi = DO_PHI && (n0 < 2048);  // q,k channels get phi(x)=exp(-x^2/2)
    #pragma unroll
    for (int i = 0; i < 2; i++) {
        #pragma unroll
        for (int j = 0; j < 4; j++) {
            if (phi) {
                #pragma unroll
                for (int e = 0; e < c[i][j].num_elements; e++) {
                    float x = c[i][j].x[e];
                    c[i][j].x[e] = expf(-0.5f * x * x);
                }
            }
            wmma::store_matrix_sync(
                C + (size_t)(m0 + wm * 32 + i * 16) * N + n0 + wn * 64 + j * 16,
                c[i][j], N, wmma::mem_row_major);
        }
    }
}

// ---------------------------------------------------------------------------
// kv partials: kv[b,h,d,e] = sum_n phiK[b,h,n,d] * V[b,h,n,e] (split over 8
// sequence chunks) plus k_sum partials. grid (64 bh, 8 chunks), 256 threads.
// ---------------------------------------------------------------------------
__global__ __launch_bounds__(256) void kv_partial_kernel(
    const float* __restrict__ qkv, float* __restrict__ kv_part,
    float* __restrict__ ks_part)
{
    const int bh = blockIdx.x;          // 0..63
    const int b  = bh >> 4;
    const int h  = bh & 15;
    const int n0 = blockIdx.y * 512;
    const int t  = threadIdx.x;

    __shared__ __align__(16) float Ks[32][64];
    __shared__ __align__(16) float Vs[32][64];

    float acc[4][4];
    #pragma unroll
    for (int i = 0; i < 4; i++)
        #pragma unroll
        for (int j = 0; j < 4; j++) acc[i][j] = 0.0f;
    float ksacc = 0.0f;

    const int d0 = (t >> 4) * 4;   // 0..60
    const int e0 = (t & 15) * 4;   // 0..60
    const int myd = t & 63;
    const int q4  = t >> 6;        // quarter: s-range [q4*8, q4*8+8)

    for (int s0 = 0; s0 < 512; s0 += 32) {
        #pragma unroll
        for (int i = 0; i < 2; i++) {
            int slot = t + 256 * i;         // 512 float4 slots
            int r  = slot >> 4;             // row within 32
            int c4 = (slot & 15) * 4;       // col
            size_t base = (size_t)(b * 4096 + n0 + s0 + r) * 3072 + h * 64 + c4;
            *(float4*)&Ks[r][c4] = *(const float4*)(qkv + base + 1024);
            *(float4*)&Vs[r][c4] = *(const float4*)(qkv + base + 2048);
        }
        __syncthreads();

        #pragma unroll 8
        for (int s = 0; s < 32; s++) {
            float kd[4], ve[4];
            #pragma unroll
            for (int i = 0; i < 4; i++) kd[i] = Ks[s][d0 + i];
            #pragma unroll
            for (int i = 0; i < 4; i++) ve[i] = Vs[s][e0 + i];
            #pragma unroll
            for (int i = 0; i < 4; i++)
                #pragma unroll
                for (int j = 0; j < 4; j++) acc[i][j] += kd[i] * ve[j];
        }
        #pragma unroll
        for (int s = q4 * 8; s < q4 * 8 + 8; s++) ksacc += Ks[s][myd];
        __syncthreads();
    }

    float* dst = kv_part + ((size_t)blockIdx.y * 64 + bh) * 4096;
    #pragma unroll
    for (int i = 0; i < 4; i++)
        #pragma unroll
        for (int j = 0; j < 4; j++)
            dst[(d0 + i) * 64 + e0 + j] = acc[i][j];

    // reduce ksum partials through smem (reuse Ks)
    ((float*)Ks)[q4 * 64 + myd] = ksacc;
    __syncthreads();
    if (t < 64) {
        float s = ((float*)Ks)[t] + ((float*)Ks)[64 + t] +
                  ((float*)Ks)[128 + t] + ((float*)Ks)[192 + t];
        ks_part[((size_t)blockIdx.y * 64 + bh) * 64 + t] = s;
    }
}

__global__ __launch_bounds__(256) void kv_reduce_kernel(
    const float* __restrict__ kv_part, const float* __restrict__ ks_part,
    float* __restrict__ kv, float* __restrict__ ks)
{
    const int bh = blockIdx.x;
    const int t  = threadIdx.x;
    for (int idx = t; idx < 4096; idx += 256) {
        float s = 0.0f;
        #pragma unroll
        for (int c = 0; c < 8; c++)
            s += kv_part[((size_t)c * 64 + bh) * 4096 + idx];
        kv[(size_t)bh * 4096 + idx] = s;
    }
    if (t < 64) {
        float s = 0.0f;
        #pragma unroll
        for (int c = 0; c < 8; c++)
            s += ks_part[((size_t)c * 64 + bh) * 64 + t];
        ks[bh * 64 + t] = s;
    }
}

// ---------------------------------------------------------------------------
// out[b,n,h*64+e] = z * sum_d phiQ[b,h,n,d]*kv[b,h,d,e],
//   z = 1/(sum_d phiQ*k_sum + 1e-6). Warp-per-row, kv cached in smem.
// grid (64 bh, 8 chunks), 256 threads (8 warps).
// ---------------------------------------------------------------------------
__global__ __launch_bounds__(256) void attn_out_kernel(
    const float* __restrict__ qkv, const float* __restrict__ kv,
    const float* __restrict__ ks, float* __restrict__ attn)
{
    const int bh = blockIdx.x;
    const int b  = bh >> 4;
    const int h  = bh & 15;
    const int t  = threadIdx.x;
    const int lane = t & 31;
    const int w    = t >> 5;

    __shared__ float kvs[64][65];
    __shared__ float kss[64];

    for (int idx = t; idx < 4096; idx += 256)
        kvs[idx >> 6][idx & 63] = kv[(size_t)bh * 4096 + idx];
    if (t < 64) kss[t] = ks[bh * 64 + t];
    __syncthreads();

    const int nbase = blockIdx.y * 512;
    for (int n = nbase + w; n < nbase + 512; n += 8) {
        size_t base = (size_t)(b * 4096 + n) * 3072 + h * 64;
        float q0 = qkv[base + lane];
        float q1 = qkv[base + 32 + lane];

        float zp = q0 * kss[lane] + q1 * kss[32 + lane];
        #pragma unroll
        for (int o = 16; o; o >>= 1) zp += __shfl_xor_sync(0xFFFFFFFFu, zp, o);
        float z = 1.0f / (zp + 1e-6f);

        float a0 = 0.0f, a1 = 0.0f;
        #pragma unroll
        for (int d = 0; d < 32; d++) {
            float qd = __shfl_sync(0xFFFFFFFFu, q0, d);
            a0 += qd * kvs[d][lane];
            a1 += qd * kvs[d][32 + lane];
        }
        #pragma unroll
        for (int d = 0; d < 32; d++) {
            float qd = __shfl_sync(0xFFFFFFFFu, q1, d);
            a0 += qd * kvs[32 + d][lane];
            a1 += qd * kvs[32 + d][32 + lane];
        }

        float* o = attn + (size_t)(b * 4096 + n) * 1024 + h * 64;
        o[lane]      = a0 * z;
        o[lane + 32] = a1 * z;
    }
}

// ---------------------------------------------------------------------------
extern "C" void kernel_launch(void* const* d_in, const int* in_sizes, int n_in,
                              void* d_out, int out_size)
{
    const float* x    = (const float*)d_in[0];  // [4,4096,1024]
    const float* Wqkv = (const float*)d_in[1];  // [3072,1024]
    const float* Wp   = (const float*)d_in[2];  // [1024,1024]
    const float* bp   = (const float*)d_in[3];  // [1024]
    float* out = (float*)d_out;                 // [4,4096,1024]

    float *qkv, *attn, *kvp, *ksp, *kv, *ks;
    cudaGetSymbolAddress((void**)&qkv,  g_qkv);
    cudaGetSymbolAddress((void**)&attn, g_attn);
    cudaGetSymbolAddress((void**)&kvp,  g_kv_part);
    cudaGetSymbolAddress((void**)&ksp,  g_ks_part);
    cudaGetSymbolAddress((void**)&kv,   g_kv);
    cudaGetSymbolAddress((void**)&ks,   g_ks);

    // 1) qkv = x @ W_qkv^T, with phi fused on q,k channels (cols < 2048)
    gemm_tf32<true, false><<<dim3(24, 128), 256>>>(x, Wqkv, nullptr, qkv,
                                                   16384, 3072, 1024);
    // 2) kv outer-product + k_sum (split-K over sequence) and reduce
    kv_partial_kernel<<<dim3(64, 8), 256>>>(qkv, kvp, ksp);
    kv_reduce_kernel<<<64, 256>>>(kvp, ksp, kv, ks);
    // 3) normalize + q @ kv  ->  attn [16384,1024]
    attn_out_kernel<<<dim3(64, 8), 256>>>(qkv, kv, ks, attn);
    // 4) out = attn @ W_proj^T + b_proj
    gemm_tf32<false, true><<<dim3(8, 128), 256>>>(attn, Wp, bp, out,
                                                  16384, 1024, 1024);
}

// round 5
// speedup vs baseline: 1.2711x; 1.2711x over previous
#include <cuda_runtime.h>
#include <cstdint>
#include <mma.h>
#include <math.h>

using namespace nvcuda;

// Problem constants: B=4, N=4096, C=1024, h=16, d=64 ; M = 16384
#define BM 128
#define BN 128
#define BK 16
#define STAGES 4
#define LDA 20                       // BK + 4 pad (floats)
#define SMEM_GEMM (STAGES * (BM + BN) * LDA * 4)

// Scratch (static __device__ globals; no allocations allowed)
__device__ float g_qkv[50331648];   // [16384, 3072]  (q|k|v), phi applied to q,k
__device__ float g_attn[16777216];  // [16384, 1024]
__device__ float g_kv_part[2097152];// [8][64][64][64]
__device__ float g_ks_part[32768];  // [8][64][64]
__device__ float g_kv[262144];      // [64][64][64]
__device__ float g_ks[4096];        // [64][64]

__device__ __forceinline__ void cp_async16(float* s, const float* g) {
    unsigned int sa = (unsigned int)__cvta_generic_to_shared(s);
    asm volatile("cp.async.cg.shared.global [%0], [%1], 16;\n" :: "r"(sa), "l"(g));
}
#define CP_COMMIT() asm volatile("cp.async.commit_group;\n" ::)
#define CP_WAIT(n)  asm volatile("cp.async.wait_group %0;\n" :: "n"(n))

// ---------------------------------------------------------------------------
// TF32 WMMA GEMM, 4-stage cp.async pipeline.
// C[m,n] = sum_k A[m,k]*W[n,k] (+bias[n]) (+phi if n<2048)
// 128x128 tile, 256 threads, warp tile 32x64 (2x4 m16n16k8 frags).
// ---------------------------------------------------------------------------
template <bool DO_PHI, bool DO_BIAS>
__global__ __launch_bounds__(256, 2) void gemm_tf32(
    const float* __restrict__ A, const float* __restrict__ W,
    const float* __restrict__ bias, float* __restrict__ C,
    int M, int N, int K)
{
    extern __shared__ float smem[];
    float* As = smem;                         // [STAGES][BM*LDA]
    float* Bs = smem + STAGES * BM * LDA;     // [STAGES][BN*LDA]
    __shared__ float bias_sm[16 * BN];

    const int t  = threadIdx.x;
    const int n0 = blockIdx.x * BN;
    const int m0 = blockIdx.y * BM;
    const int warp = t >> 5;
    const int wm = warp & 3;
    const int wn = warp >> 2;

    const float* Ablk = A + (size_t)m0 * K;
    const float* Wblk = W + (size_t)n0 * K;

    // load slots: 512 float4 per 128x16 tile, 2 per thread
    int rr[2], cc[2];
    #pragma unroll
    for (int i = 0; i < 2; i++) {
        int slot = t + 256 * i;
        rr[i] = slot >> 2;
        cc[i] = (slot & 3) * 4;
    }

    auto stage_load = [&](int kt, int s) {
        const int k0 = kt * BK;
        float* as = As + s * BM * LDA;
        float* bs = Bs + s * BN * LDA;
        #pragma unroll
        for (int i = 0; i < 2; i++) {
            cp_async16(as + rr[i] * LDA + cc[i], Ablk + (size_t)rr[i] * K + k0 + cc[i]);
            cp_async16(bs + rr[i] * LDA + cc[i], Wblk + (size_t)rr[i] * K + k0 + cc[i]);
        }
    };

    const int nk = K / BK;
    #pragma unroll
    for (int s = 0; s < STAGES - 1; s++) {
        stage_load(s, s);
        CP_COMMIT();
    }

    wmma::fragment<wmma::accumulator, 16, 16, 8, float> c[2][4];
    if (DO_BIAS) {
        for (int i = t; i < 16 * BN; i += 256)
            bias_sm[i] = bias[n0 + (i & (BN - 1))];
        __syncthreads();
        #pragma unroll
        for (int i = 0; i < 2; i++)
            #pragma unroll
            for (int j = 0; j < 4; j++)
                wmma::load_matrix_sync(c[i][j], &bias_sm[wn * 64 + j * 16], BN,
                                       wmma::mem_row_major);
    } else {
        #pragma unroll
        for (int i = 0; i < 2; i++)
            #pragma unroll
            for (int j = 0; j < 4; j++)
                wmma::fill_fragment(c[i][j], 0.0f);
    }

    for (int kt = 0; kt < nk; ++kt) {
        CP_WAIT(STAGES - 2);
        __syncthreads();

        const int nxt = kt + STAGES - 1;
        if (nxt < nk) stage_load(nxt, nxt % STAGES);
        CP_COMMIT();

        const float* as = As + (kt % STAGES) * BM * LDA;
        const float* bs = Bs + (kt % STAGES) * BN * LDA;

        #pragma unroll
        for (int kk = 0; kk < BK; kk += 8) {
            wmma::fragment<wmma::matrix_a, 16, 16, 8, wmma::precision::tf32,
                           wmma::row_major> a[2];
            wmma::fragment<wmma::matrix_b, 16, 16, 8, wmma::precision::tf32,
                           wmma::col_major> b[4];
            #pragma unroll
            for (int i = 0; i < 2; i++) {
                wmma::load_matrix_sync(a[i], as + (wm * 32 + i * 16) * LDA + kk, LDA);
                #pragma unroll
                for (int e = 0; e < a[i].num_elements; e++)
                    a[i].x[e] = wmma::__float_to_tf32(a[i].x[e]);
            }
            #pragma unroll
            for (int j = 0; j < 4; j++) {
                wmma::load_matrix_sync(b[j], bs + (wn * 64 + j * 16) * LDA + kk, LDA);
                #pragma unroll
                for (int e = 0; e < b[j].num_elements; e++)
                    b[j].x[e] = wmma::__float_to_tf32(b[j].x[e]);
            }
            #pragma unroll
            for (int i = 0; i < 2; i++)
                #pragma unroll
                for (int j = 0; j < 4; j++)
                    wmma::mma_sync(c[i][j], a[i], b[j], c[i][j]);
        }
    }

    const bool phi = DO_PHI && (n0 < 2048);
    #pragma unroll
    for (int i = 0; i < 2; i++) {
        #pragma unroll
        for (int j = 0; j < 4; j++) {
            if (phi) {
                #pragma unroll
                for (int e = 0; e < c[i][j].num_elements; e++) {
                    float x = c[i][j].x[e];
                    c[i][j].x[e] = expf(-0.5f * x * x);
                }
            }
            wmma::store_matrix_sync(
                C + (size_t)(m0 + wm * 32 + i * 16) * N + n0 + wn * 64 + j * 16,
                c[i][j], N, wmma::mem_row_major);
        }
    }
}

// ---------------------------------------------------------------------------
// kv partials: kv[b,h,d,e] = sum_n phiK * V  (8 sequence chunks) + k_sum.
// ---------------------------------------------------------------------------
__global__ __launch_bounds__(256) void kv_partial_kernel(
    const float* __restrict__ qkv, float* __restrict__ kv_part,
    float* __restrict__ ks_part)
{
    const int bh = blockIdx.x;
    const int b  = bh >> 4;
    const int h  = bh & 15;
    const int n0 = blockIdx.y * 512;
    const int t  = threadIdx.x;

    __shared__ __align__(16) float Ks[32][64];
    __shared__ __align__(16) float Vs[32][64];

    float acc[4][4];
    #pragma unroll
    for (int i = 0; i < 4; i++)
        #pragma unroll
        for (int j = 0; j < 4; j++) acc[i][j] = 0.0f;
    float ksacc = 0.0f;

    const int d0 = (t >> 4) * 4;
    const int e0 = (t & 15) * 4;
    const int myd = t & 63;
    const int q4  = t >> 6;

    for (int s0 = 0; s0 < 512; s0 += 32) {
        #pragma unroll
        for (int i = 0; i < 2; i++) {
            int slot = t + 256 * i;
            int r  = slot >> 4;
            int c4 = (slot & 15) * 4;
            size_t base = (size_t)(b * 4096 + n0 + s0 + r) * 3072 + h * 64 + c4;
            *(float4*)&Ks[r][c4] = *(const float4*)(qkv + base + 1024);
            *(float4*)&Vs[r][c4] = *(const float4*)(qkv + base + 2048);
        }
        __syncthreads();

        #pragma unroll 8
        for (int s = 0; s < 32; s++) {
            float kd[4], ve[4];
            #pragma unroll
            for (int i = 0; i < 4; i++) kd[i] = Ks[s][d0 + i];
            #pragma unroll
            for (int i = 0; i < 4; i++) ve[i] = Vs[s][e0 + i];
            #pragma unroll
            for (int i = 0; i < 4; i++)
                #pragma unroll
                for (int j = 0; j < 4; j++) acc[i][j] += kd[i] * ve[j];
        }
        #pragma unroll
        for (int s = q4 * 8; s < q4 * 8 + 8; s++) ksacc += Ks[s][myd];
        __syncthreads();
    }

    float* dst = kv_part + ((size_t)blockIdx.y * 64 + bh) * 4096;
    #pragma unroll
    for (int i = 0; i < 4; i++)
        #pragma unroll
        for (int j = 0; j < 4; j++)
            dst[(d0 + i) * 64 + e0 + j] = acc[i][j];

    ((float*)Ks)[q4 * 64 + myd] = ksacc;
    __syncthreads();
    if (t < 64) {
        float s = ((float*)Ks)[t] + ((float*)Ks)[64 + t] +
                  ((float*)Ks)[128 + t] + ((float*)Ks)[192 + t];
        ks_part[((size_t)blockIdx.y * 64 + bh) * 64 + t] = s;
    }
}

__global__ __launch_bounds__(256) void kv_reduce_kernel(
    const float* __restrict__ kv_part, const float* __restrict__ ks_part,
    float* __restrict__ kv, float* __restrict__ ks)
{
    const int bh = blockIdx.x;
    const int t  = threadIdx.x;
    for (int idx = t; idx < 4096; idx += 256) {
        float s = 0.0f;
        #pragma unroll
        for (int c = 0; c < 8; c++)
            s += kv_part[((size_t)c * 64 + bh) * 4096 + idx];
        kv[(size_t)bh * 4096 + idx] = s;
    }
    if (t < 64) {
        float s = 0.0f;
        #pragma unroll
        for (int c = 0; c < 8; c++)
            s += ks_part[((size_t)c * 64 + bh) * 64 + t];
        ks[bh * 64 + t] = s;
    }
}

// ---------------------------------------------------------------------------
// attn_out: 8 rows per warp register-blocked; kv tile LDS amortized 8x.
// out = z * (phiQ @ kv). grid (64 bh, 8 chunks), 256 threads.
// ---------------------------------------------------------------------------
__global__ __launch_bounds__(256) void attn_out_kernel(
    const float* __restrict__ qkv, const float* __restrict__ kv,
    const float* __restrict__ ks, float* __restrict__ attn)
{
    const int bh = blockIdx.x;
    const int b  = bh >> 4;
    const int h  = bh & 15;
    const int t  = threadIdx.x;
    const int lane = t & 31;
    const int w    = t >> 5;

    __shared__ float kvs[64][65];
    __shared__ float kss[64];

    for (int idx = t; idx < 4096; idx += 256)
        kvs[idx >> 6][idx & 63] = kv[(size_t)bh * 4096 + idx];
    if (t < 64) kss[t] = ks[bh * 64 + t];
    __syncthreads();

    const int nbase = blockIdx.y * 512 + w * 64;   // warp covers 64 rows
    for (int g = 0; g < 8; ++g) {
        const int n = nbase + g * 8;               // 8 rows this group
        float q0[8], q1[8], a0[8], a1[8], z[8];
        #pragma unroll
        for (int r = 0; r < 8; r++) {
            size_t base = (size_t)(b * 4096 + n + r) * 3072 + h * 64;
            q0[r] = qkv[base + lane];
            q1[r] = qkv[base + 32 + lane];
            a0[r] = 0.0f; a1[r] = 0.0f;
        }
        #pragma unroll
        for (int r = 0; r < 8; r++) {
            float zp = q0[r] * kss[lane] + q1[r] * kss[32 + lane];
            #pragma unroll
            for (int o = 16; o; o >>= 1) zp += __shfl_xor_sync(0xFFFFFFFFu, zp, o);
            z[r] = 1.0f / (zp + 1e-6f);
        }

        #pragma unroll 4
        for (int d = 0; d < 32; d++) {
            float kv0 = kvs[d][lane];
            float kv1 = kvs[d][32 + lane];
            #pragma unroll
            for (int r = 0; r < 8; r++) {
                float qd = __shfl_sync(0xFFFFFFFFu, q0[r], d);
                a0[r] += qd * kv0;
                a1[r] += qd * kv1;
            }
        }
        #pragma unroll 4
        for (int d = 0; d < 32; d++) {
            float kv0 = kvs[32 + d][lane];
            float kv1 = kvs[32 + d][32 + lane];
            #pragma unroll
            for (int r = 0; r < 8; r++) {
                float qd = __shfl_sync(0xFFFFFFFFu, q1[r], d);
                a0[r] += qd * kv0;
                a1[r] += qd * kv1;
            }
        }

        #pragma unroll
        for (int r = 0; r < 8; r++) {
            float* o = attn + (size_t)(b * 4096 + n + r) * 1024 + h * 64;
            o[lane]      = a0[r] * z[r];
            o[lane + 32] = a1[r] * z[r];
        }
    }
}

// ---------------------------------------------------------------------------
extern "C" void kernel_launch(void* const* d_in, const int* in_sizes, int n_in,
                              void* d_out, int out_size)
{
    const float* x    = (const float*)d_in[0];  // [4,4096,1024]
    const float* Wqkv = (const float*)d_in[1];  // [3072,1024]
    const float* Wp   = (const float*)d_in[2];  // [1024,1024]
    const float* bp   = (const float*)d_in[3];  // [1024]
    float* out = (float*)d_out;                 // [4,4096,1024]

    float *qkv, *attn, *kvp, *ksp, *kv, *ks;
    cudaGetSymbolAddress((void**)&qkv,  g_qkv);
    cudaGetSymbolAddress((void**)&attn, g_attn);
    cudaGetSymbolAddress((void**)&kvp,  g_kv_part);
    cudaGetSymbolAddress((void**)&ksp,  g_ks_part);
    cudaGetSymbolAddress((void**)&kv,   g_kv);
    cudaGetSymbolAddress((void**)&ks,   g_ks);

    cudaFuncSetAttribute(gemm_tf32<true, false>,
                         cudaFuncAttributeMaxDynamicSharedMemorySize, SMEM_GEMM);
    cudaFuncSetAttribute(gemm_tf32<false, true>,
                         cudaFuncAttributeMaxDynamicSharedMemorySize, SMEM_GEMM);

    // 1) qkv = x @ W_qkv^T, phi fused on q,k (cols < 2048)
    gemm_tf32<true, false><<<dim3(24, 128), 256, SMEM_GEMM>>>(
        x, Wqkv, nullptr, qkv, 16384, 3072, 1024);
    // 2) kv outer-product + k_sum partials, then reduce
    kv_partial_kernel<<<dim3(64, 8), 256>>>(qkv, kvp, ksp);
    kv_reduce_kernel<<<64, 256>>>(kvp, ksp, kv, ks);
    // 3) normalize + q @ kv -> attn
    attn_out_kernel<<<dim3(64, 8), 256>>>(qkv, kv, ks, attn);
    // 4) out = attn @ W_proj^T + b_proj
    gemm_tf32<false, true><<<dim3(8, 128), 256, SMEM_GEMM>>>(
        attn, Wp, bp, out, 16384, 1024, 1024);
}

// round 9
// speedup vs baseline: 2.2531x; 1.7725x over previous
#include <cuda_runtime.h>
#include <cstdint>
#include <math.h>

// Problem constants: B=4, N=4096, C=1024, h=16, d=64 ; M = 16384, K = 1024
#define BM 128
#define BN 128
#define BK 16
#define STAGES 4
#define LDA 20                       // BK + 4 pad (floats); 80B row stride
#define SMEM_GEMM (STAGES * (BM + BN) * LDA * 4)

// Scratch (static __device__ globals; no allocations allowed)
__device__ float g_qkv[50331648];   // [16384, 3072]  (q|k|v), phi applied to q,k
__device__ float g_attn[16777216];  // [16384, 1024]
__device__ float g_kv_part[2097152];// [8][64][64][64]
__device__ float g_ks_part[32768];  // [8][64][64]
__device__ float g_kv[262144];      // [64][64][64]
__device__ float g_ks[4096];        // [64][64]

// ---------------------------------------------------------------------------
// PTX helpers (sm_80-baseline ISA only; target is plain sm_100)
// ---------------------------------------------------------------------------
static __device__ __forceinline__ void cp_async16(float* s, const float* g) {
    unsigned int sa = (unsigned int)__cvta_generic_to_shared(s);
    asm volatile("cp.async.cg.shared.global [%0], [%1], 16;\n" :: "r"(sa), "l"(g));
}
#define CP_COMMIT() asm volatile("cp.async.commit_group;\n" ::)
#define CP_WAIT(n)  asm volatile("cp.async.wait_group %0;\n" :: "n"(n))

static __device__ __forceinline__ void ldsm4(uint32_t r[4], const float* p) {
    unsigned int sa = (unsigned int)__cvta_generic_to_shared(p);
    asm volatile("ldmatrix.sync.aligned.m8n8.x4.shared.b16 {%0,%1,%2,%3}, [%4];"
                 : "=r"(r[0]), "=r"(r[1]), "=r"(r[2]), "=r"(r[3]) : "r"(sa));
}
static __device__ __forceinline__ void cvt_tf32(uint32_t& x) {
    asm volatile("cvt.rna.tf32.f32 %0, %0;" : "+r"(x));
}
static __device__ __forceinline__ void mma16n8k8(
    float d[4], const uint32_t a[4], uint32_t b0, uint32_t b1)
{
    asm volatile(
        "mma.sync.aligned.m16n8k8.row.col.f32.tf32.tf32.f32 "
        "{%0,%1,%2,%3}, {%4,%5,%6,%7}, {%8,%9}, {%0,%1,%2,%3};"
        : "+f"(d[0]), "+f"(d[1]), "+f"(d[2]), "+f"(d[3])
        : "r"(a[0]), "r"(a[1]), "r"(a[2]), "r"(a[3]), "r"(b0), "r"(b1));
}

// ---------------------------------------------------------------------------
// TF32 mma.sync GEMM, 4-stage cp.async pipeline, ldmatrix operand loads.
// C[m,n] = sum_k A[m,k]*W[n,k] (+bias[n]) (+phi if n0<2048)
// 128x128 CTA tile, 256 threads (8 warps: 4M x 2N), warp tile 32x64.
// ---------------------------------------------------------------------------
template <bool DO_PHI, bool DO_BIAS>
__global__ __launch_bounds__(256, 1) void gemm_tf32(
    const float* __restrict__ A, const float* __restrict__ W,
    const float* __restrict__ bias, float* __restrict__ C,
    int M, int N, int K)
{
    extern __shared__ float smem[];
    float* As = smem;                         // [STAGES][BM*LDA]
    float* Bs = smem + STAGES * BM * LDA;     // [STAGES][BN*LDA]
    __shared__ float bias_sm[BN];

    const int t  = threadIdx.x;
    const int n0 = blockIdx.x * BN;
    const int m0 = blockIdx.y * BM;
    const int warp = t >> 5;
    const int lane = t & 31;
    const int wm = warp & 3;       // 32 rows each
    const int wn = warp >> 2;      // 64 cols each
    const int lr = lane & 7;       // ldmatrix row within group
    const int lg = lane >> 3;      // ldmatrix group 0..3

    const float* Ablk = A + (size_t)m0 * K;
    const float* Wblk = W + (size_t)n0 * K;

    if (DO_BIAS && t < BN) bias_sm[t] = bias[n0 + t];

    // cp.async load slots: 512 float4 per 128x16 tile, 2 per thread
    int rr[2], cc[2];
    #pragma unroll
    for (int i = 0; i < 2; i++) {
        int slot = t + 256 * i;
        rr[i] = slot >> 2;
        cc[i] = (slot & 3) * 4;
    }

    auto stage_load = [&](int kt, int s) {
        const int k0 = kt * BK;
        float* as = As + s * BM * LDA;
        float* bs = Bs + s * BN * LDA;
        #pragma unroll
        for (int i = 0; i < 2; i++) {
            cp_async16(as + rr[i] * LDA + cc[i], Ablk + (size_t)rr[i] * K + k0 + cc[i]);
            cp_async16(bs + rr[i] * LDA + cc[i], Wblk + (size_t)rr[i] * K + k0 + cc[i]);
        }
    };

    const int nk = K / BK;
    #pragma unroll
    for (int s = 0; s < STAGES - 1; s++) {
        stage_load(s, s);
        CP_COMMIT();
    }

    float d[2][8][4];
    #pragma unroll
    for (int i = 0; i < 2; i++)
        #pragma unroll
        for (int j = 0; j < 8; j++)
            #pragma unroll
            for (int e = 0; e < 4; e++) d[i][j][e] = 0.0f;

    // per-thread ldmatrix base offsets (within a stage tile)
    //  A frag i at (wm*32 + i*16, kk): row = +lr + (lg&1)*8 ; col = kk + (lg>>1)*4
    //  B pair j at (wn*64 + j*16, kk): row = +lr + (lg>>1)*8 ; col = kk + (lg&1)*4
    const int a_row = wm * 32 + lr + (lg & 1) * 8;
    const int a_col = (lg >> 1) * 4;
    const int b_row = wn * 64 + lr + (lg >> 1) * 8;
    const int b_col = (lg & 1) * 4;

    for (int kt = 0; kt < nk; ++kt) {
        CP_WAIT(STAGES - 2);
        __syncthreads();

        const int nxt = kt + STAGES - 1;
        if (nxt < nk) stage_load(nxt, nxt % STAGES);
        CP_COMMIT();

        const float* as = As + (kt % STAGES) * BM * LDA;
        const float* bs = Bs + (kt % STAGES) * BN * LDA;

        #pragma unroll
        for (int kk = 0; kk < BK; kk += 8) {
            uint32_t a[2][4], b[4][4];
            #pragma unroll
            for (int i = 0; i < 2; i++) {
                ldsm4(a[i], as + (a_row + i * 16) * LDA + kk + a_col);
                #pragma unroll
                for (int e = 0; e < 4; e++) cvt_tf32(a[i][e]);
            }
            #pragma unroll
            for (int j = 0; j < 4; j++) {
                ldsm4(b[j], bs + (b_row + j * 16) * LDA + kk + b_col);
                #pragma unroll
                for (int e = 0; e < 4; e++) cvt_tf32(b[j][e]);
            }
            #pragma unroll
            for (int i = 0; i < 2; i++)
                #pragma unroll
                for (int jj = 0; jj < 8; jj++)
                    mma16n8k8(d[i][jj], a[i],
                              b[jj >> 1][(jj & 1) * 2], b[jj >> 1][(jj & 1) * 2 + 1]);
        }
        __syncthreads();
    }

    // ---- epilogue: direct register->global stores (float2 per half-frag) ----
    const bool phi = DO_PHI && (n0 < 2048);
    const int er = lane >> 2;            // row within frag (0..7)
    const int ec = (lane & 3) * 2;       // col within n8 (0,2,4,6)
    #pragma unroll
    for (int i = 0; i < 2; i++) {
        const int grow = m0 + wm * 32 + i * 16 + er;
        #pragma unroll
        for (int jj = 0; jj < 8; jj++) {
            const int lcol = wn * 64 + jj * 8 + ec;
            float v[4];
            #pragma unroll
            for (int e = 0; e < 4; e++) v[e] = d[i][jj][e];
            if (phi) {
                #pragma unroll
                for (int e = 0; e < 4; e++) v[e] = expf(-0.5f * v[e] * v[e]);
            }
            if (DO_BIAS) {
                v[0] += bias_sm[lcol];     v[1] += bias_sm[lcol + 1];
                v[2] += bias_sm[lcol];     v[3] += bias_sm[lcol + 1];
            }
            *(float2*)(C + (size_t)grow * N + n0 + lcol) = make_float2(v[0], v[1]);
            *(float2*)(C + (size_t)(grow + 8) * N + n0 + lcol) = make_float2(v[2], v[3]);
        }
    }
}

// ---------------------------------------------------------------------------
// kv partials: kv[b,h,d,e] = sum_n phiK * V  (8 sequence chunks) + k_sum.
// ---------------------------------------------------------------------------
__global__ __launch_bounds__(256) void kv_partial_kernel(
    const float* __restrict__ qkv, float* __restrict__ kv_part,
    float* __restrict__ ks_part)
{
    const int bh = blockIdx.x;
    const int b  = bh >> 4;
    const int h  = bh & 15;
    const int n0 = blockIdx.y * 512;
    const int t  = threadIdx.x;

    __shared__ __align__(16) float Ks[32][64];
    __shared__ __align__(16) float Vs[32][64];

    float acc[4][4];
    #pragma unroll
    for (int i = 0; i < 4; i++)
        #pragma unroll
        for (int j = 0; j < 4; j++) acc[i][j] = 0.0f;
    float ksacc = 0.0f;

    const int d0 = (t >> 4) * 4;
    const int e0 = (t & 15) * 4;
    const int myd = t & 63;
    const int q4  = t >> 6;

    for (int s0 = 0; s0 < 512; s0 += 32) {
        #pragma unroll
        for (int i = 0; i < 2; i++) {
            int slot = t + 256 * i;
            int r  = slot >> 4;
            int c4 = (slot & 15) * 4;
            size_t base = (size_t)(b * 4096 + n0 + s0 + r) * 3072 + h * 64 + c4;
            *(float4*)&Ks[r][c4] = *(const float4*)(qkv + base + 1024);
            *(float4*)&Vs[r][c4] = *(const float4*)(qkv + base + 2048);
        }
        __syncthreads();

        #pragma unroll 8
        for (int s = 0; s < 32; s++) {
            float kd[4], ve[4];
            #pragma unroll
            for (int i = 0; i < 4; i++) kd[i] = Ks[s][d0 + i];
            #pragma unroll
            for (int i = 0; i < 4; i++) ve[i] = Vs[s][e0 + i];
            #pragma unroll
            for (int i = 0; i < 4; i++)
                #pragma unroll
                for (int j = 0; j < 4; j++) acc[i][j] += kd[i] * ve[j];
        }
        #pragma unroll
        for (int s = q4 * 8; s < q4 * 8 + 8; s++) ksacc += Ks[s][myd];
        __syncthreads();
    }

    float* dst = kv_part + ((size_t)blockIdx.y * 64 + bh) * 4096;
    #pragma unroll
    for (int i = 0; i < 4; i++)
        #pragma unroll
        for (int j = 0; j < 4; j++)
            dst[(d0 + i) * 64 + e0 + j] = acc[i][j];

    ((float*)Ks)[q4 * 64 + myd] = ksacc;
    __syncthreads();
    if (t < 64) {
        float s = ((float*)Ks)[t] + ((float*)Ks)[64 + t] +
                  ((float*)Ks)[128 + t] + ((float*)Ks)[192 + t];
        ks_part[((size_t)blockIdx.y * 64 + bh) * 64 + t] = s;
    }
}

__global__ __launch_bounds__(256) void kv_reduce_kernel(
    const float* __restrict__ kv_part, const float* __restrict__ ks_part,
    float* __restrict__ kv, float* __restrict__ ks)
{
    const int bh = blockIdx.x;
    const int t  = threadIdx.x;
    for (int idx = t; idx < 4096; idx += 256) {
        float s = 0.0f;
        #pragma unroll
        for (int c = 0; c < 8; c++)
            s += kv_part[((size_t)c * 64 + bh) * 4096 + idx];
        kv[(size_t)bh * 4096 + idx] = s;
    }
    if (t < 64) {
        float s = 0.0f;
        #pragma unroll
        for (int c = 0; c < 8; c++)
            s += ks_part[((size_t)c * 64 + bh) * 64 + t];
        ks[bh * 64 + t] = s;
    }
}

// ---------------------------------------------------------------------------
// attn_out: 8 rows per warp register-blocked; kv tile in smem.
// ---------------------------------------------------------------------------
__global__ __launch_bounds__(256) void attn_out_kernel(
    const float* __restrict__ qkv, const float* __restrict__ kv,
    const float* __restrict__ ks, float* __restrict__ attn)
{
    const int bh = blockIdx.x;
    const int b  = bh >> 4;
    const int h  = bh & 15;
    const int t  = threadIdx.x;
    const int lane = t & 31;
    const int w    = t >> 5;

    __shared__ float kvs[64][65];
    __shared__ float kss[64];

    for (int idx = t; idx < 4096; idx += 256)
        kvs[idx >> 6][idx & 63] = kv[(size_t)bh * 4096 + idx];
    if (t < 64) kss[t] = ks[bh * 64 + t];
    __syncthreads();

    const int nbase = blockIdx.y * 512 + w * 64;
    for (int g = 0; g < 8; ++g) {
        const int n = nbase + g * 8;
        float q0[8], q1[8], a0[8], a1[8], z[8];
        #pragma unroll
        for (int r = 0; r < 8; r++) {
            size_t base = (size_t)(b * 4096 + n + r) * 3072 + h * 64;
            q0[r] = qkv[base + lane];
            q1[r] = qkv[base + 32 + lane];
            a0[r] = 0.0f; a1[r] = 0.0f;
        }
        #pragma unroll
        for (int r = 0; r < 8; r++) {
            float zp = q0[r] * kss[lane] + q1[r] * kss[32 + lane];
            #pragma unroll
            for (int o = 16; o; o >>= 1) zp += __shfl_xor_sync(0xFFFFFFFFu, zp, o);
            z[r] = 1.0f / (zp + 1e-6f);
        }

        #pragma unroll 4
        for (int d = 0; d < 32; d++) {
            float kv0 = kvs[d][lane];
            float kv1 = kvs[d][32 + lane];
            #pragma unroll
            for (int r = 0; r < 8; r++) {
                float qd = __shfl_sync(0xFFFFFFFFu, q0[r], d);
                a0[r] += qd * kv0;
                a1[r] += qd * kv1;
            }
        }
        #pragma unroll 4
        for (int d = 0; d < 32; d++) {
            float kv0 = kvs[32 + d][lane];
            float kv1 = kvs[32 + d][32 + lane];
            #pragma unroll
            for (int r = 0; r < 8; r++) {
                float qd = __shfl_sync(0xFFFFFFFFu, q1[r], d);
                a0[r] += qd * kv0;
                a1[r] += qd * kv1;
            }
        }

        #pragma unroll
        for (int r = 0; r < 8; r++) {
            float* o = attn + (size_t)(b * 4096 + n + r) * 1024 + h * 64;
            o[lane]      = a0[r] * z[r];
            o[lane + 32] = a1[r] * z[r];
        }
    }
}

// ---------------------------------------------------------------------------
extern "C" void kernel_launch(void* const* d_in, const int* in_sizes, int n_in,
                              void* d_out, int out_size)
{
    const float* x    = (const float*)d_in[0];  // [4,4096,1024]
    const float* Wqkv = (const float*)d_in[1];  // [3072,1024]
    const float* Wp   = (const float*)d_in[2];  // [1024,1024]
    const float* bp   = (const float*)d_in[3];  // [1024]
    float* out = (float*)d_out;                 // [4,4096,1024]

    float *qkv, *attn, *kvp, *ksp, *kv, *ks;
    cudaGetSymbolAddress((void**)&qkv,  g_qkv);
    cudaGetSymbolAddress((void**)&attn, g_attn);
    cudaGetSymbolAddress((void**)&kvp,  g_kv_part);
    cudaGetSymbolAddress((void**)&ksp,  g_ks_part);
    cudaGetSymbolAddress((void**)&kv,   g_kv);
    cudaGetSymbolAddress((void**)&ks,   g_ks);

    cudaFuncSetAttribute(gemm_tf32<true, false>,
                         cudaFuncAttributeMaxDynamicSharedMemorySize, SMEM_GEMM);
    cudaFuncSetAttribute(gemm_tf32<false, true>,
                         cudaFuncAttributeMaxDynamicSharedMemorySize, SMEM_GEMM);

    // 1) qkv = x @ W_qkv^T, phi fused on q,k (cols < 2048)
    gemm_tf32<true, false><<<dim3(24, 128), 256, SMEM_GEMM>>>(
        x, Wqkv, nullptr, qkv, 16384, 3072, 1024);
    // 2) kv outer-product + k_sum partials, then reduce
    kv_partial_kernel<<<dim3(64, 8), 256>>>(qkv, kvp, ksp);
    kv_reduce_kernel<<<64, 256>>>(kvp, ksp, kv, ks);
    // 3) normalize + q @ kv -> attn
    attn_out_kernel<<<dim3(64, 8), 256>>>(qkv, kv, ks, attn);
    // 4) out = attn @ W_proj^T + b_proj
    gemm_tf32<false, true><<<dim3(8, 128), 256, SMEM_GEMM>>>(
        attn, Wp, bp, out, 16384, 1024, 1024);
}